// round 3
// baseline (speedup 1.0000x reference)
#include <cuda_runtime.h>
#include <cstdint>

// Problem constants (shapes fixed by the dataset)
#define NMAX 100000
#define EMAX 1600000
#define H 64

// ---------------- device scratch (no allocations allowed) ----------------
__device__ float g_bufA[NMAX * H];
__device__ float g_bufB[NMAX * H];
__device__ float g_deg[NMAX];      // degree, then dinv = rsqrt(deg)
__device__ int   g_cnt[NMAX];      // in-degree (edge count) histogram
__device__ int   g_off[NMAX + 1];  // CSR offsets by target node
__device__ int   g_cur[NMAX];      // scatter cursors
__device__ int2  g_epack[EMAX];    // (src_row, bitcast(norm)) grouped by target
__device__ int   g_bsum[128];      // scan block sums

// ---------------- degree / CSR build ----------------
__global__ void k_init(int n) {
    int i = blockIdx.x * blockDim.x + threadIdx.x;
    if (i < n) { g_deg[i] = 1.0f; g_cnt[i] = 0; }   // self-loop weight 1
}

__global__ void k_count(const int* __restrict__ col, const float* __restrict__ ew, int e) {
    int i = blockIdx.x * blockDim.x + threadIdx.x;
    if (i < e) {
        int c = col[i];
        atomicAdd(&g_deg[c], ew[i]);
        atomicAdd(&g_cnt[c], 1);
    }
}

__global__ void k_dinv(int n) {
    int i = blockIdx.x * blockDim.x + threadIdx.x;
    if (i < n) g_deg[i] = rsqrtf(g_deg[i]);   // deg >= 1 always (self loop)
}

__global__ void k_scan1(int n) {
    __shared__ int s[1024];
    int i = blockIdx.x * 1024 + threadIdx.x;
    int v = (i < n) ? g_cnt[i] : 0;
    s[threadIdx.x] = v;
    __syncthreads();
    #pragma unroll
    for (int o = 1; o < 1024; o <<= 1) {
        int t = (threadIdx.x >= o) ? s[threadIdx.x - o] : 0;
        __syncthreads();
        s[threadIdx.x] += t;
        __syncthreads();
    }
    if (i < n) g_off[i] = s[threadIdx.x] - v;           // exclusive within block
    if (threadIdx.x == 1023) g_bsum[blockIdx.x] = s[1023];
}

__global__ void k_scan2(int nb) {
    if (threadIdx.x == 0 && blockIdx.x == 0) {
        int run = 0;
        for (int i = 0; i < nb; i++) { int t = g_bsum[i]; g_bsum[i] = run; run += t; }
    }
}

__global__ void k_scan3(int n, int e) {
    int i = blockIdx.x * blockDim.x + threadIdx.x;
    if (i < n) {
        int o = g_off[i] + g_bsum[i >> 10];
        g_off[i] = o;
        g_cur[i] = o;
    }
    if (i == 0) g_off[n] = e;
}

__global__ void k_build(const int* __restrict__ row, const int* __restrict__ col,
                        const float* __restrict__ ew, int e) {
    int i = blockIdx.x * blockDim.x + threadIdx.x;
    if (i < e) {
        int r = row[i], c = col[i];
        int p = atomicAdd(&g_cur[c], 1);
        float w = g_deg[r] * ew[i] * g_deg[c];          // dinv[row]*ew*dinv[col]
        g_epack[p] = make_int2(r, __float_as_int(w));
    }
}

// ---------------- aggregation: warp per target node, atomic-free ----------------
// out[node] = relu( dinv[node]^2 * hin[node] + sum_j norm_j * hin[src_j] )
__global__ void k_agg(const float* __restrict__ hin, float* __restrict__ hout, int n) {
    int warp = (blockIdx.x * blockDim.x + threadIdx.x) >> 5;
    int lane = threadIdx.x & 31;
    if (warp >= n) return;
    float d = g_deg[warp];
    float sl = d * d;
    float2 v = *(const float2*)(hin + (size_t)warp * H + lane * 2);
    float ax = v.x * sl, ay = v.y * sl;
    int j = g_off[warp], epos = g_off[warp + 1];
    for (; j < epos; ++j) {
        int2 p = __ldg(&g_epack[j]);
        float w = __int_as_float(p.y);
        float2 hv = *(const float2*)(hin + (size_t)p.x * H + lane * 2);
        ax = fmaf(w, hv.x, ax);
        ay = fmaf(w, hv.y, ay);
    }
    ax = fmaxf(ax, 0.0f);
    ay = fmaxf(ay, 0.0f);
    *(float2*)(hout + (size_t)warp * H + lane * 2) = make_float2(ax, ay);
}

// ---------------- GEMM: C[row,col] = A[N,64] @ W[64, ldw] (+bias, optional relu) ----
// Block: 64 rows x 64 cols tile, 128 threads, each thread 4x8 micro-tile.
__global__ void gemm_tile(const float* __restrict__ A, const float* __restrict__ W,
                          int ldw, const float* __restrict__ bias,
                          float* __restrict__ C, int ldc, int nrows, int relu_flag) {
    __shared__ float As[64][65];
    __shared__ float Ws[64][64];
    int tid = threadIdx.x;               // 128 threads
    int row0 = blockIdx.x * 64;
    int col0 = blockIdx.y * 64;

    // Load A tile (64x64 floats) via float4, zero-pad past nrows
    for (int i = tid; i < 64 * 16; i += 128) {
        int r = i >> 4, c4 = (i & 15) << 2;
        float4 v = make_float4(0.f, 0.f, 0.f, 0.f);
        int gr = row0 + r;
        if (gr < nrows) v = *(const float4*)(A + (size_t)gr * 64 + c4);
        As[r][c4] = v.x; As[r][c4 + 1] = v.y; As[r][c4 + 2] = v.z; As[r][c4 + 3] = v.w;
    }
    // Load W tile (64x64)
    for (int i = tid; i < 64 * 16; i += 128) {
        int r = i >> 4, c4 = (i & 15) << 2;
        float4 v = *(const float4*)(W + (size_t)r * ldw + col0 + c4);
        *(float4*)(&Ws[r][c4]) = v;
    }
    __syncthreads();

    int rg = tid >> 3;       // 0..15
    int cg = tid & 7;        // 0..7
    int r0 = rg * 4, c0 = cg * 8;

    float acc[4][8];
    #pragma unroll
    for (int i = 0; i < 4; i++)
        #pragma unroll
        for (int j = 0; j < 8; j++) acc[i][j] = 0.f;

    #pragma unroll
    for (int k = 0; k < 64; k++) {
        float4 w0 = *(const float4*)(&Ws[k][c0]);
        float4 w1 = *(const float4*)(&Ws[k][c0 + 4]);
        #pragma unroll
        for (int i = 0; i < 4; i++) {
            float a = As[r0 + i][k];
            acc[i][0] = fmaf(a, w0.x, acc[i][0]);
            acc[i][1] = fmaf(a, w0.y, acc[i][1]);
            acc[i][2] = fmaf(a, w0.z, acc[i][2]);
            acc[i][3] = fmaf(a, w0.w, acc[i][3]);
            acc[i][4] = fmaf(a, w1.x, acc[i][4]);
            acc[i][5] = fmaf(a, w1.y, acc[i][5]);
            acc[i][6] = fmaf(a, w1.z, acc[i][6]);
            acc[i][7] = fmaf(a, w1.w, acc[i][7]);
        }
    }

    float bb[8];
    if (bias) {
        #pragma unroll
        for (int j = 0; j < 8; j++) bb[j] = bias[col0 + c0 + j];
    } else {
        #pragma unroll
        for (int j = 0; j < 8; j++) bb[j] = 0.f;
    }

    #pragma unroll
    for (int i = 0; i < 4; i++) {
        int gr = row0 + r0 + i;
        if (gr < nrows) {
            float o[8];
            #pragma unroll
            for (int j = 0; j < 8; j++) {
                float t = acc[i][j] + bb[j];
                o[j] = relu_flag ? fmaxf(t, 0.f) : t;
            }
            float* cp = C + (size_t)gr * ldc + col0 + c0;
            *(float4*)(cp)     = make_float4(o[0], o[1], o[2], o[3]);
            *(float4*)(cp + 4) = make_float4(o[4], o[5], o[6], o[7]);
        }
    }
}

// ---------------- launch ----------------
extern "C" void kernel_launch(void* const* d_in, const int* in_sizes, int n_in,
                              void* d_out, int out_size) {
    const float* x  = (const float*)d_in[0];
    const int*   ei = (const int*)d_in[1];
    const float* ew = (const float*)d_in[2];
    const float* W1 = (const float*)d_in[3];
    const float* W2 = (const float*)d_in[4];
    const float* A1 = (const float*)d_in[5];
    const float* b1 = (const float*)d_in[6];
    const float* A2 = (const float*)d_in[7];
    const float* b2 = (const float*)d_in[8];

    int n = in_sizes[0] / 64;       // 100000
    int e = in_sizes[2];            // 1600000
    const int* row = ei;            // edge_index[0]
    const int* col = ei + e;        // edge_index[1]

    float* out   = (float*)d_out;
    float* r_out = out;                       // [n, 12*32] = [n, 384]
    float* h_out = out + (size_t)n * 384;     // [n, 64]

    float *bufA, *bufB;
    cudaGetSymbolAddress((void**)&bufA, g_bufA);
    cudaGetSymbolAddress((void**)&bufB, g_bufB);

    int gn = (n + 255) / 256;
    int ge = (e + 255) / 256;
    int nb = (n + 1023) / 1024;
    int mtiles = (n + 63) / 64;
    int gagg = (n * 32 + 255) / 256;

    // CSR-by-target build (reused by both GCN layers)
    k_init<<<gn, 256>>>(n);
    k_count<<<ge, 256>>>(col, ew, e);
    k_dinv<<<gn, 256>>>(n);
    k_scan1<<<nb, 1024>>>(n);
    k_scan2<<<1, 32>>>(nb);
    k_scan3<<<gn, 256>>>(n, e);
    k_build<<<ge, 256>>>(row, col, ew, e);

    // GCN layer 1: h0 = x @ W1 ; h1 = relu(aggregate(h0))
    gemm_tile<<<dim3(mtiles, 1), 128>>>(x, W1, 64, nullptr, bufA, 64, n, 0);
    k_agg<<<gagg, 256>>>(bufA, bufB, n);

    // GCN layer 2: t = h1 @ W2 ; h = relu(aggregate(t))  -> written to d_out h region
    gemm_tile<<<dim3(mtiles, 1), 128>>>(bufB, W2, 64, nullptr, bufA, 64, n, 0);
    k_agg<<<gagg, 256>>>(bufA, h_out, n);

    // Readout: t = relu(h @ A1 + b1) ; r = t @ A2 + b2
    gemm_tile<<<dim3(mtiles, 1), 128>>>(h_out, A1, 64, b1, bufB, 64, n, 1);
    gemm_tile<<<dim3(mtiles, 6), 128>>>(bufB, A2, 384, b2, r_out, 384, n, 0);
}

// round 4
// speedup vs baseline: 1.0669x; 1.0669x over previous
#include <cuda_runtime.h>
#include <cstdint>

#define NMAX 100000
#define EMAX 1600000
#define H 64

// ---------------- device scratch (no allocations allowed) ----------------
__device__ float g_bufA[NMAX * H];
__device__ float g_bufB[NMAX * H];
__device__ float g_deg[NMAX];      // degree, then dinv = rsqrt(deg)
__device__ int   g_cnt[NMAX];      // in-degree (edge count) histogram
__device__ int   g_off[NMAX + 1];  // CSR offsets by target node
__device__ int   g_cur[NMAX];      // scatter cursors
__device__ int2  g_epack[EMAX];    // (src_row, bitcast(norm)) grouped by target
__device__ int   g_bsum[128];      // scan block sums

// ---------------- packed f32x2 FMA helpers (sm_103a FFMA2) ----------------
typedef unsigned long long u64;

__device__ __forceinline__ u64 pack2(float a) {
    u64 r;
    unsigned int u = __float_as_uint(a);
    asm("mov.b64 %0, {%1, %1};" : "=l"(r) : "r"(u));
    return r;
}
#define FMA2(d, a, b) asm("fma.rn.f32x2 %0, %1, %2, %0;" : "+l"(d) : "l"(a), "l"(b))

__device__ __forceinline__ void unpack2(u64 v, float& lo, float& hi) {
    unsigned int l, h;
    asm("mov.b64 {%0, %1}, %2;" : "=r"(l), "=r"(h) : "l"(v));
    lo = __uint_as_float(l);
    hi = __uint_as_float(h);
}

// ---------------- degree / CSR build ----------------
__global__ void k_init(int n) {
    int i = blockIdx.x * blockDim.x + threadIdx.x;
    if (i < n) { g_deg[i] = 1.0f; g_cnt[i] = 0; }   // self-loop weight 1
}

__global__ void k_count(const int* __restrict__ col, const float* __restrict__ ew, int e) {
    int i = blockIdx.x * blockDim.x + threadIdx.x;
    if (i < e) {
        int c = col[i];
        atomicAdd(&g_deg[c], ew[i]);
        atomicAdd(&g_cnt[c], 1);
    }
}

__global__ void k_scan1(int n) {
    __shared__ int s[1024];
    int i = blockIdx.x * 1024 + threadIdx.x;
    int v = (i < n) ? g_cnt[i] : 0;
    s[threadIdx.x] = v;
    __syncthreads();
    #pragma unroll
    for (int o = 1; o < 1024; o <<= 1) {
        int t = (threadIdx.x >= o) ? s[threadIdx.x - o] : 0;
        __syncthreads();
        s[threadIdx.x] += t;
        __syncthreads();
    }
    if (i < n) g_off[i] = s[threadIdx.x] - v;           // exclusive within block
    if (threadIdx.x == 1023) g_bsum[blockIdx.x] = s[1023];
}

__global__ void k_scan2(int nb) {
    if (threadIdx.x == 0 && blockIdx.x == 0) {
        int run = 0;
        for (int i = 0; i < nb; i++) { int t = g_bsum[i]; g_bsum[i] = run; run += t; }
    }
}

__global__ void k_scan3(int n, int e) {
    int i = blockIdx.x * blockDim.x + threadIdx.x;
    if (i < n) {
        int o = g_off[i] + g_bsum[i >> 10];
        g_off[i] = o;
        g_cur[i] = o;
        g_deg[i] = rsqrtf(g_deg[i]);   // dinv (deg >= 1 always, self-loop)
    }
    if (i == 0) g_off[n] = e;
}

__global__ void k_build(const int* __restrict__ row, const int* __restrict__ col,
                        const float* __restrict__ ew, int e) {
    int i = blockIdx.x * blockDim.x + threadIdx.x;
    if (i < e) {
        int r = row[i], c = col[i];
        int p = atomicAdd(&g_cur[c], 1);
        float w = g_deg[r] * ew[i] * g_deg[c];          // dinv[row]*ew*dinv[col]
        g_epack[p] = make_int2(r, __float_as_int(w));
    }
}

// ---------------- aggregation: warp per target node, atomic-free ----------------
// out[node] = relu( dinv[node]^2 * hin[node] + sum_j norm_j * hin[src_j] )
__global__ void k_agg(const float* __restrict__ hin, float* __restrict__ hout, int n) {
    int warp = (blockIdx.x * blockDim.x + threadIdx.x) >> 5;
    int lane = threadIdx.x & 31;
    if (warp >= n) return;
    float d = g_deg[warp];
    float sl = d * d;
    const float2* base = (const float2*)hin + lane;
    float2 v = base[(size_t)warp * 32];
    float ax = v.x * sl, ay = v.y * sl;
    int j = g_off[warp], jend = g_off[warp + 1];
    // unrolled x4 for memory-level parallelism
    for (; j + 4 <= jend; j += 4) {
        int2 p0 = __ldg(&g_epack[j]);
        int2 p1 = __ldg(&g_epack[j + 1]);
        int2 p2 = __ldg(&g_epack[j + 2]);
        int2 p3 = __ldg(&g_epack[j + 3]);
        float2 h0 = base[(size_t)p0.x * 32];
        float2 h1 = base[(size_t)p1.x * 32];
        float2 h2 = base[(size_t)p2.x * 32];
        float2 h3 = base[(size_t)p3.x * 32];
        float w0 = __int_as_float(p0.y), w1 = __int_as_float(p1.y);
        float w2 = __int_as_float(p2.y), w3 = __int_as_float(p3.y);
        ax = fmaf(w0, h0.x, ax); ay = fmaf(w0, h0.y, ay);
        ax = fmaf(w1, h1.x, ax); ay = fmaf(w1, h1.y, ay);
        ax = fmaf(w2, h2.x, ax); ay = fmaf(w2, h2.y, ay);
        ax = fmaf(w3, h3.x, ax); ay = fmaf(w3, h3.y, ay);
    }
    for (; j < jend; ++j) {
        int2 p = __ldg(&g_epack[j]);
        float w = __int_as_float(p.y);
        float2 hv = base[(size_t)p.x * 32];
        ax = fmaf(w, hv.x, ax);
        ay = fmaf(w, hv.y, ay);
    }
    ax = fmaxf(ax, 0.0f);
    ay = fmaxf(ay, 0.0f);
    *((float2*)hout + lane + (size_t)warp * 32) = make_float2(ax, ay);
}

// ---------------- shared GEMM micro-kernel (4 rows x 8 cols per thread) -------
// acc[i][jp] holds output cols (c0+2jp, c0+2jp+1) for row r0+i, packed f32x2.
__device__ __forceinline__ void mm_core(const float (*As)[65], const float (*Ws)[64],
                                        int r0, int c0, u64 acc[4][4]) {
    #pragma unroll 8
    for (int k = 0; k < 64; k++) {
        const u64* wr = (const u64*)&Ws[k][c0];
        u64 w0 = wr[0], w1 = wr[1], w2 = wr[2], w3 = wr[3];
        #pragma unroll
        for (int i = 0; i < 4; i++) {
            u64 ap = pack2(As[r0 + i][k]);
            FMA2(acc[i][0], ap, w0);
            FMA2(acc[i][1], ap, w1);
            FMA2(acc[i][2], ap, w2);
            FMA2(acc[i][3], ap, w3);
        }
    }
}

// ---------------- GEMM: C = A[N,64] @ W[64,64] (no bias/relu) -----------------
__global__ void gemm_tile(const float* __restrict__ A, const float* __restrict__ W,
                          float* __restrict__ C, int nrows) {
    __shared__ __align__(16) float As[64][65];
    __shared__ __align__(16) float Ws[64][64];
    int tid = threadIdx.x;               // 128 threads
    int row0 = blockIdx.x * 64;

    for (int i = tid; i < 64 * 16; i += 128) {
        int r = i >> 4, c4 = (i & 15) << 2;
        float4 v = make_float4(0.f, 0.f, 0.f, 0.f);
        int gr = row0 + r;
        if (gr < nrows) v = *(const float4*)(A + (size_t)gr * 64 + c4);
        As[r][c4] = v.x; As[r][c4 + 1] = v.y; As[r][c4 + 2] = v.z; As[r][c4 + 3] = v.w;
        *(float4*)(&Ws[r][c4]) = *(const float4*)(W + (size_t)r * 64 + c4);
    }
    __syncthreads();

    int r0 = (tid >> 3) * 4, c0 = (tid & 7) * 8;
    u64 acc[4][4] = {};
    mm_core(As, Ws, r0, c0, acc);

    #pragma unroll
    for (int i = 0; i < 4; i++) {
        int gr = row0 + r0 + i;
        if (gr < nrows) {
            float o[8];
            #pragma unroll
            for (int jp = 0; jp < 4; jp++) unpack2(acc[i][jp], o[2 * jp], o[2 * jp + 1]);
            float* cp = C + (size_t)gr * 64 + c0;
            *(float4*)(cp)     = make_float4(o[0], o[1], o[2], o[3]);
            *(float4*)(cp + 4) = make_float4(o[4], o[5], o[6], o[7]);
        }
    }
}

// ---------------- fused readout: r = relu(h@A1+b1)@A2 + b2 --------------------
// One block = 64 rows. Stage 1 builds T (64x64) in smem, stage 2 sweeps the 6
// 64-wide column tiles of A2 against the resident T.
__global__ void readout_fused(const float* __restrict__ hmat,
                              const float* __restrict__ A1, const float* __restrict__ b1,
                              const float* __restrict__ A2, const float* __restrict__ b2,
                              float* __restrict__ r_out, int nrows) {
    __shared__ __align__(16) float Hs[64][65];   // h tile, later reused as T
    __shared__ __align__(16) float Ws[64][64];   // A1, then A2 column tiles
    int tid = threadIdx.x;               // 128 threads
    int row0 = blockIdx.x * 64;
    int r0 = (tid >> 3) * 4, c0 = (tid & 7) * 8;

    for (int i = tid; i < 64 * 16; i += 128) {
        int r = i >> 4, c4 = (i & 15) << 2;
        float4 v = make_float4(0.f, 0.f, 0.f, 0.f);
        int gr = row0 + r;
        if (gr < nrows) v = *(const float4*)(hmat + (size_t)gr * 64 + c4);
        Hs[r][c4] = v.x; Hs[r][c4 + 1] = v.y; Hs[r][c4 + 2] = v.z; Hs[r][c4 + 3] = v.w;
        *(float4*)(&Ws[r][c4]) = *(const float4*)(A1 + (size_t)r * 64 + c4);
    }
    __syncthreads();

    // stage 1: T = relu(H @ A1 + b1)
    {
        u64 acc[4][4] = {};
        mm_core(Hs, Ws, r0, c0, acc);
        __syncthreads();                 // all reads of Hs complete before overwrite
        #pragma unroll
        for (int i = 0; i < 4; i++) {
            #pragma unroll
            for (int jp = 0; jp < 4; jp++) {
                float lo, hi;
                unpack2(acc[i][jp], lo, hi);
                Hs[r0 + i][c0 + 2 * jp]     = fmaxf(lo + b1[c0 + 2 * jp], 0.f);
                Hs[r0 + i][c0 + 2 * jp + 1] = fmaxf(hi + b1[c0 + 2 * jp + 1], 0.f);
            }
        }
    }

    // stage 2: sweep A2 column tiles
    for (int ct = 0; ct < 6; ct++) {
        __syncthreads();                 // prior reads of Ws (and T writes) done
        for (int i = tid; i < 64 * 16; i += 128) {
            int r = i >> 4, c4 = (i & 15) << 2;
            *(float4*)(&Ws[r][c4]) = *(const float4*)(A2 + (size_t)r * 384 + ct * 64 + c4);
        }
        __syncthreads();

        u64 acc[4][4] = {};
        mm_core(Hs, Ws, r0, c0, acc);

        int gc = ct * 64 + c0;
        float bb[8];
        #pragma unroll
        for (int j = 0; j < 8; j++) bb[j] = b2[gc + j];

        #pragma unroll
        for (int i = 0; i < 4; i++) {
            int gr = row0 + r0 + i;
            if (gr < nrows) {
                float o[8];
                #pragma unroll
                for (int jp = 0; jp < 4; jp++) unpack2(acc[i][jp], o[2 * jp], o[2 * jp + 1]);
                #pragma unroll
                for (int j = 0; j < 8; j++) o[j] += bb[j];
                float* cp = r_out + (size_t)gr * 384 + gc;
                *(float4*)(cp)     = make_float4(o[0], o[1], o[2], o[3]);
                *(float4*)(cp + 4) = make_float4(o[4], o[5], o[6], o[7]);
            }
        }
    }
}

// ---------------- launch ----------------
extern "C" void kernel_launch(void* const* d_in, const int* in_sizes, int n_in,
                              void* d_out, int out_size) {
    const float* x  = (const float*)d_in[0];
    const int*   ei = (const int*)d_in[1];
    const float* ew = (const float*)d_in[2];
    const float* W1 = (const float*)d_in[3];
    const float* W2 = (const float*)d_in[4];
    const float* A1 = (const float*)d_in[5];
    const float* b1 = (const float*)d_in[6];
    const float* A2 = (const float*)d_in[7];
    const float* b2 = (const float*)d_in[8];

    int n = in_sizes[0] / 64;       // 100000
    int e = in_sizes[2];            // 1600000
    const int* row = ei;            // edge_index[0]
    const int* col = ei + e;        // edge_index[1]

    float* out   = (float*)d_out;
    float* r_out = out;                       // [n, 384]
    float* h_out = out + (size_t)n * 384;     // [n, 64]

    float *bufA, *bufB;
    cudaGetSymbolAddress((void**)&bufA, g_bufA);
    cudaGetSymbolAddress((void**)&bufB, g_bufB);

    int gn = (n + 255) / 256;
    int ge = (e + 255) / 256;
    int nb = (n + 1023) / 1024;
    int mtiles = (n + 63) / 64;
    int gagg = (n * 32 + 255) / 256;

    // CSR-by-target build (reused by both GCN layers)
    k_init<<<gn, 256>>>(n);
    k_count<<<ge, 256>>>(col, ew, e);
    k_scan1<<<nb, 1024>>>(n);
    k_scan2<<<1, 32>>>(nb);
    k_scan3<<<gn, 256>>>(n, e);          // also finalizes dinv
    k_build<<<ge, 256>>>(row, col, ew, e);

    // GCN layer 1: h0 = x @ W1 ; h1 = relu(aggregate(h0))
    gemm_tile<<<mtiles, 128>>>(x, W1, bufA, n);
    k_agg<<<gagg, 256>>>(bufA, bufB, n);

    // GCN layer 2: t = h1 @ W2 ; h = relu(aggregate(t))
    gemm_tile<<<mtiles, 128>>>(bufB, W2, bufA, n);
    k_agg<<<gagg, 256>>>(bufA, h_out, n);

    // Readout: r = relu(h @ A1 + b1) @ A2 + b2
    readout_fused<<<mtiles, 128>>>(h_out, A1, b1, A2, b2, r_out, n);
}

// round 5
// speedup vs baseline: 1.2702x; 1.1905x over previous
#include <cuda_runtime.h>
#include <cstdint>

#define NMAX 100000
#define EMAX 1600000
#define H 64

// ---------------- device scratch (no allocations allowed) ----------------
__device__ float g_bufA[NMAX * H];
__device__ float g_bufB[NMAX * H];
__device__ float g_deg[NMAX];      // degree, then dinv = rsqrt(deg)
__device__ int   g_cnt[NMAX];      // in-degree (edge count) histogram
__device__ int   g_off[NMAX + 1];  // CSR offsets by target node
__device__ int   g_cur[NMAX];      // scatter cursors
__device__ int2  g_epack[EMAX];    // (src_row, bitcast(norm)) grouped by target
__device__ int   g_bsum[128];      // scan block sums

// ---------------- packed f32x2 FMA helpers (sm_103a FFMA2) ----------------
typedef unsigned long long u64;

__device__ __forceinline__ u64 pack2(float a) {
    u64 r;
    unsigned int u = __float_as_uint(a);
    asm("mov.b64 %0, {%1, %1};" : "=l"(r) : "r"(u));
    return r;
}
#define FMA2(d, a, b) asm("fma.rn.f32x2 %0, %1, %2, %0;" : "+l"(d) : "l"(a), "l"(b))

__device__ __forceinline__ void unpack2(u64 v, float& lo, float& hi) {
    unsigned int l, h;
    asm("mov.b64 {%0, %1}, %2;" : "=r"(l), "=r"(h) : "l"(v));
    lo = __uint_as_float(l);
    hi = __uint_as_float(h);
}

// ---------------- degree / CSR build ----------------
__global__ void k_init(int n) {
    int i = blockIdx.x * blockDim.x + threadIdx.x;
    if (i < n) { g_deg[i] = 1.0f; g_cnt[i] = 0; }   // self-loop weight 1
}

__global__ void k_count(const int* __restrict__ col, const float* __restrict__ ew, int e) {
    int i = blockIdx.x * blockDim.x + threadIdx.x;
    if (i < e) {
        int c = col[i];
        atomicAdd(&g_deg[c], ew[i]);
        atomicAdd(&g_cnt[c], 1);
    }
}

__global__ void k_scan1(int n) {
    __shared__ int s[1024];
    int i = blockIdx.x * 1024 + threadIdx.x;
    int v = (i < n) ? g_cnt[i] : 0;
    s[threadIdx.x] = v;
    __syncthreads();
    #pragma unroll
    for (int o = 1; o < 1024; o <<= 1) {
        int t = (threadIdx.x >= o) ? s[threadIdx.x - o] : 0;
        __syncthreads();
        s[threadIdx.x] += t;
        __syncthreads();
    }
    if (i < n) g_off[i] = s[threadIdx.x] - v;           // exclusive within block
    if (threadIdx.x == 1023) g_bsum[blockIdx.x] = s[1023];
}

// parallel exclusive scan of block sums (nb <= 128), one block of 128 threads
__global__ void k_scan2(int nb) {
    __shared__ int s[128];
    int v = (threadIdx.x < nb) ? g_bsum[threadIdx.x] : 0;
    s[threadIdx.x] = v;
    __syncthreads();
    #pragma unroll
    for (int o = 1; o < 128; o <<= 1) {
        int t = (threadIdx.x >= o) ? s[threadIdx.x - o] : 0;
        __syncthreads();
        s[threadIdx.x] += t;
        __syncthreads();
    }
    if (threadIdx.x < nb) g_bsum[threadIdx.x] = s[threadIdx.x] - v;   // exclusive
}

__global__ void k_scan3(int n, int e) {
    int i = blockIdx.x * blockDim.x + threadIdx.x;
    if (i < n) {
        int o = g_off[i] + g_bsum[i >> 10];
        g_off[i] = o;
        g_cur[i] = o;
        g_deg[i] = rsqrtf(g_deg[i]);   // dinv (deg >= 1 always, self-loop)
    }
    if (i == 0) g_off[n] = e;
}

__global__ void k_build(const int* __restrict__ row, const int* __restrict__ col,
                        const float* __restrict__ ew, int e) {
    int i = blockIdx.x * blockDim.x + threadIdx.x;
    if (i < e) {
        int r = row[i], c = col[i];
        int p = atomicAdd(&g_cur[c], 1);
        float w = g_deg[r] * ew[i] * g_deg[c];          // dinv[row]*ew*dinv[col]
        g_epack[p] = make_int2(r, __float_as_int(w));
    }
}

// ---------------- aggregation: warp per target node, atomic-free ----------------
// out[node] = dinv[node]^2 * hin[node] + sum_j norm_j * hin[src_j]   (no relu:
// relu moved into the following GEMM via S(XW)=(SX)W reassociation)
__global__ void k_agg(const float* __restrict__ hin, float* __restrict__ hout, int n) {
    int warp = (blockIdx.x * blockDim.x + threadIdx.x) >> 5;
    int lane = threadIdx.x & 31;
    if (warp >= n) return;
    float d = g_deg[warp];
    float sl = d * d;
    const float2* base = (const float2*)hin + lane;
    float2 v = base[(size_t)warp * 32];
    float ax = v.x * sl, ay = v.y * sl;
    int j = g_off[warp], jend = g_off[warp + 1];
    for (; j + 4 <= jend; j += 4) {
        int2 p0 = __ldg(&g_epack[j]);
        int2 p1 = __ldg(&g_epack[j + 1]);
        int2 p2 = __ldg(&g_epack[j + 2]);
        int2 p3 = __ldg(&g_epack[j + 3]);
        float2 h0 = base[(size_t)p0.x * 32];
        float2 h1 = base[(size_t)p1.x * 32];
        float2 h2 = base[(size_t)p2.x * 32];
        float2 h3 = base[(size_t)p3.x * 32];
        float w0 = __int_as_float(p0.y), w1 = __int_as_float(p1.y);
        float w2 = __int_as_float(p2.y), w3 = __int_as_float(p3.y);
        ax = fmaf(w0, h0.x, ax); ay = fmaf(w0, h0.y, ay);
        ax = fmaf(w1, h1.x, ax); ay = fmaf(w1, h1.y, ay);
        ax = fmaf(w2, h2.x, ax); ay = fmaf(w2, h2.y, ay);
        ax = fmaf(w3, h3.x, ax); ay = fmaf(w3, h3.y, ay);
    }
    for (; j < jend; ++j) {
        int2 p = __ldg(&g_epack[j]);
        float w = __int_as_float(p.y);
        float2 hv = base[(size_t)p.x * 32];
        ax = fmaf(w, hv.x, ax);
        ay = fmaf(w, hv.y, ay);
    }
    *((float2*)hout + lane + (size_t)warp * 32) = make_float2(ax, ay);
}

// ---------------- shared GEMM micro-kernel: 8 rows x 8 cols per thread -------
// 128 threads cover a 128x64 output tile. acc[i][jp] = cols (c0+2jp, c0+2jp+1)
// of row r0+i, packed f32x2.
__device__ __forceinline__ void mm_core8(const float (*As)[65], const float (*Ws)[64],
                                         int r0, int c0, u64 acc[8][4]) {
    #pragma unroll 4
    for (int k = 0; k < 64; k++) {
        const u64* wr = (const u64*)&Ws[k][c0];
        u64 w0 = wr[0], w1 = wr[1], w2 = wr[2], w3 = wr[3];
        #pragma unroll
        for (int i = 0; i < 8; i++) {
            u64 ap = pack2(As[r0 + i][k]);
            FMA2(acc[i][0], ap, w0);
            FMA2(acc[i][1], ap, w1);
            FMA2(acc[i][2], ap, w2);
            FMA2(acc[i][3], ap, w3);
        }
    }
}

// load helpers for dynamic-smem tiles
__device__ __forceinline__ void load_A_tile(float (*As)[65], const float* A,
                                            int row0, int nrows, int tid) {
    for (int i = tid; i < 128 * 16; i += 128) {
        int r = i >> 4, c4 = (i & 15) << 2;
        float4 v = make_float4(0.f, 0.f, 0.f, 0.f);
        int gr = row0 + r;
        if (gr < nrows) v = *(const float4*)(A + (size_t)gr * 64 + c4);
        As[r][c4] = v.x; As[r][c4 + 1] = v.y; As[r][c4 + 2] = v.z; As[r][c4 + 3] = v.w;
    }
}
__device__ __forceinline__ void load_W_tile(float (*Ws)[64], const float* W,
                                            int ldw, int col0, int tid) {
    for (int i = tid; i < 64 * 16; i += 128) {
        int r = i >> 4, c4 = (i & 15) << 2;
        *(float4*)(&Ws[r][c4]) = *(const float4*)(W + (size_t)r * ldw + col0 + c4);
    }
}

#define SM_BYTES ((128 * 65 + 64 * 64) * 4)

// ---------------- GEMM: C = [relu](A[N,64] @ W[64,64]) -----------------------
__global__ __launch_bounds__(128) void gemm128(const float* __restrict__ A,
                                               const float* __restrict__ W,
                                               float* __restrict__ C, int nrows,
                                               int relu_flag) {
    extern __shared__ float sm[];
    float (*As)[65] = (float(*)[65])sm;
    float (*Ws)[64] = (float(*)[64])(sm + 128 * 65);
    int tid = threadIdx.x;
    int row0 = blockIdx.x * 128;

    load_A_tile(As, A, row0, nrows, tid);
    load_W_tile(Ws, W, 64, 0, tid);
    __syncthreads();

    int r0 = (tid >> 3) * 8, c0 = (tid & 7) * 8;
    u64 acc[8][4] = {};
    mm_core8(As, Ws, r0, c0, acc);

    #pragma unroll
    for (int i = 0; i < 8; i++) {
        int gr = row0 + r0 + i;
        if (gr < nrows) {
            float o[8];
            #pragma unroll
            for (int jp = 0; jp < 4; jp++) unpack2(acc[i][jp], o[2 * jp], o[2 * jp + 1]);
            if (relu_flag) {
                #pragma unroll
                for (int j = 0; j < 8; j++) o[j] = fmaxf(o[j], 0.f);
            }
            float* cp = C + (size_t)gr * 64 + c0;
            *(float4*)(cp)     = make_float4(o[0], o[1], o[2], o[3]);
            *(float4*)(cp + 4) = make_float4(o[4], o[5], o[6], o[7]);
        }
    }
}

// ---------------- mega readout: h = relu(Z@W2); r = relu(h@A1+b1)@A2 + b2 ----
// One block = 128 rows resident in smem across all three stages.
__global__ __launch_bounds__(128) void readout_mega(
        const float* __restrict__ Z, const float* __restrict__ W2,
        const float* __restrict__ A1, const float* __restrict__ b1,
        const float* __restrict__ A2, const float* __restrict__ b2,
        float* __restrict__ h_out, float* __restrict__ r_out, int nrows) {
    extern __shared__ float sm[];
    float (*Hs)[65] = (float(*)[65])sm;             // Z -> h -> T
    float (*Ws)[64] = (float(*)[64])(sm + 128 * 65);
    int tid = threadIdx.x;
    int row0 = blockIdx.x * 128;
    int r0 = (tid >> 3) * 8, c0 = (tid & 7) * 8;

    load_A_tile(Hs, Z, row0, nrows, tid);
    load_W_tile(Ws, W2, 64, 0, tid);
    __syncthreads();

    // stage 0: h = relu(Z @ W2) -> Hs and global h_out
    {
        u64 acc[8][4] = {};
        mm_core8(Hs, Ws, r0, c0, acc);
        __syncthreads();
        #pragma unroll
        for (int i = 0; i < 8; i++) {
            float o[8];
            #pragma unroll
            for (int jp = 0; jp < 4; jp++) unpack2(acc[i][jp], o[2 * jp], o[2 * jp + 1]);
            #pragma unroll
            for (int j = 0; j < 8; j++) o[j] = fmaxf(o[j], 0.f);
            #pragma unroll
            for (int j = 0; j < 8; j++) Hs[r0 + i][c0 + j] = o[j];
            int gr = row0 + r0 + i;
            if (gr < nrows) {
                float* cp = h_out + (size_t)gr * 64 + c0;
                *(float4*)(cp)     = make_float4(o[0], o[1], o[2], o[3]);
                *(float4*)(cp + 4) = make_float4(o[4], o[5], o[6], o[7]);
            }
        }
        load_W_tile(Ws, A1, 64, 0, tid);
        __syncthreads();
    }

    // stage 1: T = relu(h @ A1 + b1) -> Hs
    {
        u64 acc[8][4] = {};
        mm_core8(Hs, Ws, r0, c0, acc);
        float bb[8];
        #pragma unroll
        for (int j = 0; j < 8; j++) bb[j] = b1[c0 + j];
        __syncthreads();
        #pragma unroll
        for (int i = 0; i < 8; i++) {
            #pragma unroll
            for (int jp = 0; jp < 4; jp++) {
                float lo, hi;
                unpack2(acc[i][jp], lo, hi);
                Hs[r0 + i][c0 + 2 * jp]     = fmaxf(lo + bb[2 * jp], 0.f);
                Hs[r0 + i][c0 + 2 * jp + 1] = fmaxf(hi + bb[2 * jp + 1], 0.f);
            }
        }
    }

    // stage 2: r = T @ A2 + b2, swept over 6 column tiles of A2
    for (int ct = 0; ct < 6; ct++) {
        __syncthreads();            // prior mm_core reads of Ws (and Hs writes) done
        load_W_tile(Ws, A2, 384, ct * 64, tid);
        __syncthreads();

        u64 acc[8][4] = {};
        mm_core8(Hs, Ws, r0, c0, acc);

        int gc = ct * 64 + c0;
        float bb[8];
        #pragma unroll
        for (int j = 0; j < 8; j++) bb[j] = b2[gc + j];

        #pragma unroll
        for (int i = 0; i < 8; i++) {
            int gr = row0 + r0 + i;
            if (gr < nrows) {
                float o[8];
                #pragma unroll
                for (int jp = 0; jp < 4; jp++) unpack2(acc[i][jp], o[2 * jp], o[2 * jp + 1]);
                #pragma unroll
                for (int j = 0; j < 8; j++) o[j] += bb[j];
                float* cp = r_out + (size_t)gr * 384 + gc;
                *(float4*)(cp)     = make_float4(o[0], o[1], o[2], o[3]);
                *(float4*)(cp + 4) = make_float4(o[4], o[5], o[6], o[7]);
            }
        }
    }
}

// ---------------- launch ----------------
extern "C" void kernel_launch(void* const* d_in, const int* in_sizes, int n_in,
                              void* d_out, int out_size) {
    const float* x  = (const float*)d_in[0];
    const int*   ei = (const int*)d_in[1];
    const float* ew = (const float*)d_in[2];
    const float* W1 = (const float*)d_in[3];
    const float* W2 = (const float*)d_in[4];
    const float* A1 = (const float*)d_in[5];
    const float* b1 = (const float*)d_in[6];
    const float* A2 = (const float*)d_in[7];
    const float* b2 = (const float*)d_in[8];

    int n = in_sizes[0] / 64;       // 100000
    int e = in_sizes[2];            // 1600000
    const int* row = ei;            // edge_index[0]
    const int* col = ei + e;        // edge_index[1]

    float* out   = (float*)d_out;
    float* r_out = out;                       // [n, 384]
    float* h_out = out + (size_t)n * 384;     // [n, 64]

    float *bufA, *bufB;
    cudaGetSymbolAddress((void**)&bufA, g_bufA);
    cudaGetSymbolAddress((void**)&bufB, g_bufB);

    static int smem_set = 0;
    if (!smem_set) {
        cudaFuncSetAttribute(gemm128, cudaFuncAttributeMaxDynamicSharedMemorySize, SM_BYTES);
        cudaFuncSetAttribute(readout_mega, cudaFuncAttributeMaxDynamicSharedMemorySize, SM_BYTES);
        smem_set = 1;
    }

    int gn = (n + 255) / 256;
    int ge = (e + 255) / 256;
    int nb = (n + 1023) / 1024;
    int mt = (n + 127) / 128;
    int gagg = (n * 32 + 255) / 256;

    // CSR-by-target build (shared by both GCN layers)
    k_init<<<gn, 256>>>(n);
    k_count<<<ge, 256>>>(col, ew, e);
    k_scan1<<<nb, 1024>>>(n);
    k_scan2<<<1, 128>>>(nb);
    k_scan3<<<gn, 256>>>(n, e);          // also finalizes dinv
    k_build<<<ge, 256>>>(row, col, ew, e);

    // Layer 1 (reassociated): Y = S·x ; h1 = relu(Y @ W1)
    k_agg<<<gagg, 256>>>(x, bufA, n);
    gemm128<<<mt, 128, SM_BYTES>>>(bufA, W1, bufB, n, 1);

    // Layer 2 + readout (fused): Z = S·h1 ; h = relu(Z@W2) ;
    // r = relu(h@A1+b1)@A2 + b2
    k_agg<<<gagg, 256>>>(bufB, bufA, n);
    readout_mega<<<mt, 128, SM_BYTES>>>(bufA, W2, A1, b1, A2, b2, h_out, r_out, n);
}

// round 8
// speedup vs baseline: 1.4130x; 1.1124x over previous
#include <cuda_runtime.h>
#include <cstdint>

#define NMAX 100000
#define EMAX 1600000
#define H 64

typedef unsigned long long u64;

// ---------------- device scratch (no allocations allowed) ----------------
__device__ float g_bufA[NMAX * H];
__device__ float g_bufB[NMAX * H];
__device__ float g_A2t[64 * 384];  // A2 tf32-rounded, same [64][384] layout (B[k][n])
__device__ float g_deg[NMAX];      // degree, then dinv = rsqrt(deg)
__device__ int   g_cnt[NMAX];      // in-degree (edge count) histogram
__device__ int   g_off[NMAX + 1];  // CSR offsets by target node
__device__ int   g_cur[NMAX];      // scatter cursors
__device__ int2  g_epack[EMAX];    // (src_row, bitcast(norm)) grouped by target
__device__ int   g_bsum[128];      // scan block sums

// ---------------- packed f32x2 FMA helpers (sm_103a FFMA2) ----------------
__device__ __forceinline__ u64 pack2(float a) {
    u64 r;
    unsigned int u = __float_as_uint(a);
    asm("mov.b64 %0, {%1, %1};" : "=l"(r) : "r"(u));
    return r;
}
#define FMA2(d, a, b) asm("fma.rn.f32x2 %0, %1, %2, %0;" : "+l"(d) : "l"(a), "l"(b))

__device__ __forceinline__ void unpack2(u64 v, float& lo, float& hi) {
    unsigned int l, h;
    asm("mov.b64 {%0, %1}, %2;" : "=r"(l), "=r"(h) : "l"(v));
    lo = __uint_as_float(l);
    hi = __uint_as_float(h);
}

__device__ __forceinline__ float to_tf32(float x) {
    unsigned int u;
    asm("cvt.rna.tf32.f32 %0, %1;" : "=r"(u) : "f"(x));
    return __uint_as_float(u);
}

// warp-level tf32 MMA (sm_80+ baseline feature, valid for compute_103)
__device__ __forceinline__ void mma_tf32(float c[4], const unsigned a[4],
                                         const unsigned b[2]) {
    asm volatile(
        "mma.sync.aligned.m16n8k8.row.col.f32.tf32.tf32.f32 "
        "{%0,%1,%2,%3}, {%4,%5,%6,%7}, {%8,%9}, {%0,%1,%2,%3};"
        : "+f"(c[0]), "+f"(c[1]), "+f"(c[2]), "+f"(c[3])
        : "r"(a[0]), "r"(a[1]), "r"(a[2]), "r"(a[3]), "r"(b[0]), "r"(b[1]));
}

// ---------------- degree / CSR build ----------------
__global__ void k_init(int n) {
    int i = blockIdx.x * blockDim.x + threadIdx.x;
    if (i < n) { g_deg[i] = 1.0f; g_cnt[i] = 0; }   // self-loop weight 1
}

__global__ void k_count(const int* __restrict__ col, const float* __restrict__ ew, int e) {
    int i = blockIdx.x * blockDim.x + threadIdx.x;
    if (i < e) {
        int c = col[i];
        atomicAdd(&g_deg[c], ew[i]);
        atomicAdd(&g_cnt[c], 1);
    }
}

__global__ void k_scan1(int n) {
    __shared__ int s[1024];
    int i = blockIdx.x * 1024 + threadIdx.x;
    int v = (i < n) ? g_cnt[i] : 0;
    s[threadIdx.x] = v;
    __syncthreads();
    #pragma unroll
    for (int o = 1; o < 1024; o <<= 1) {
        int t = (threadIdx.x >= o) ? s[threadIdx.x - o] : 0;
        __syncthreads();
        s[threadIdx.x] += t;
        __syncthreads();
    }
    if (i < n) g_off[i] = s[threadIdx.x] - v;
    if (threadIdx.x == 1023) g_bsum[blockIdx.x] = s[1023];
}

__global__ void k_scan2(int nb) {
    __shared__ int s[128];
    int v = (threadIdx.x < nb) ? g_bsum[threadIdx.x] : 0;
    s[threadIdx.x] = v;
    __syncthreads();
    #pragma unroll
    for (int o = 1; o < 128; o <<= 1) {
        int t = (threadIdx.x >= o) ? s[threadIdx.x - o] : 0;
        __syncthreads();
        s[threadIdx.x] += t;
        __syncthreads();
    }
    if (threadIdx.x < nb) g_bsum[threadIdx.x] = s[threadIdx.x] - v;
}

__global__ void k_scan3(int n, int e) {
    int i = blockIdx.x * blockDim.x + threadIdx.x;
    if (i < n) {
        int o = g_off[i] + g_bsum[i >> 10];
        g_off[i] = o;
        g_cur[i] = o;
        g_deg[i] = rsqrtf(g_deg[i]);
    }
    if (i == 0) g_off[n] = e;
}

__global__ void k_build(const int* __restrict__ row, const int* __restrict__ col,
                        const float* __restrict__ ew, int e) {
    int i = blockIdx.x * blockDim.x + threadIdx.x;
    if (i < e) {
        int r = row[i], c = col[i];
        int p = atomicAdd(&g_cur[c], 1);
        float w = g_deg[r] * ew[i] * g_deg[c];
        g_epack[p] = make_int2(r, __float_as_int(w));
    }
}

// ---------------- A2 tf32 pre-rounding (layout unchanged: B[k][n]) ----------
__global__ void k_tr(const float* __restrict__ A2) {
    int i = blockIdx.x * blockDim.x + threadIdx.x;
    if (i < 64 * 384) g_A2t[i] = to_tf32(A2[i]);
}

// ---------------- aggregation: warp per target node, atomic-free ------------
__global__ void k_agg(const float* __restrict__ hin, float* __restrict__ hout, int n) {
    int warp = (blockIdx.x * blockDim.x + threadIdx.x) >> 5;
    int lane = threadIdx.x & 31;
    if (warp >= n) return;
    float d = g_deg[warp];
    float sl = d * d;
    const float2* base = (const float2*)hin + lane;
    float2 v = base[(size_t)warp * 32];
    float ax = v.x * sl, ay = v.y * sl;
    int j = g_off[warp], jend = g_off[warp + 1];
    for (; j + 4 <= jend; j += 4) {
        int2 p0 = __ldg(&g_epack[j]);
        int2 p1 = __ldg(&g_epack[j + 1]);
        int2 p2 = __ldg(&g_epack[j + 2]);
        int2 p3 = __ldg(&g_epack[j + 3]);
        float2 h0 = base[(size_t)p0.x * 32];
        float2 h1 = base[(size_t)p1.x * 32];
        float2 h2 = base[(size_t)p2.x * 32];
        float2 h3 = base[(size_t)p3.x * 32];
        float w0 = __int_as_float(p0.y), w1 = __int_as_float(p1.y);
        float w2 = __int_as_float(p2.y), w3 = __int_as_float(p3.y);
        ax = fmaf(w0, h0.x, ax); ay = fmaf(w0, h0.y, ay);
        ax = fmaf(w1, h1.x, ax); ay = fmaf(w1, h1.y, ay);
        ax = fmaf(w2, h2.x, ax); ay = fmaf(w2, h2.y, ay);
        ax = fmaf(w3, h3.x, ax); ay = fmaf(w3, h3.y, ay);
    }
    for (; j < jend; ++j) {
        int2 p = __ldg(&g_epack[j]);
        float w = __int_as_float(p.y);
        float2 hv = base[(size_t)p.x * 32];
        ax = fmaf(w, hv.x, ax);
        ay = fmaf(w, hv.y, ay);
    }
    *((float2*)hout + lane + (size_t)warp * 32) = make_float2(ax, ay);
}

// ---------------- fp32 GEMM micro-kernel: 8 rows x 8 cols per thread --------
__device__ __forceinline__ void mm_core8(const float (*As)[65], const float (*Ws)[64],
                                         int r0, int c0, u64 acc[8][4]) {
    #pragma unroll 4
    for (int k = 0; k < 64; k++) {
        const u64* wr = (const u64*)&Ws[k][c0];
        u64 w0 = wr[0], w1 = wr[1], w2 = wr[2], w3 = wr[3];
        #pragma unroll
        for (int i = 0; i < 8; i++) {
            u64 ap = pack2(As[r0 + i][k]);
            FMA2(acc[i][0], ap, w0);
            FMA2(acc[i][1], ap, w1);
            FMA2(acc[i][2], ap, w2);
            FMA2(acc[i][3], ap, w3);
        }
    }
}

__device__ __forceinline__ void load_A_tile(float (*As)[65], const float* A,
                                            int row0, int nrows, int tid) {
    for (int i = tid; i < 128 * 16; i += 128) {
        int r = i >> 4, c4 = (i & 15) << 2;
        float4 v = make_float4(0.f, 0.f, 0.f, 0.f);
        int gr = row0 + r;
        if (gr < nrows) v = *(const float4*)(A + (size_t)gr * 64 + c4);
        As[r][c4] = v.x; As[r][c4 + 1] = v.y; As[r][c4 + 2] = v.z; As[r][c4 + 3] = v.w;
    }
}
__device__ __forceinline__ void load_W_tile(float (*Ws)[64], const float* W,
                                            int ldw, int col0, int tid) {
    for (int i = tid; i < 64 * 16; i += 128) {
        int r = i >> 4, c4 = (i & 15) << 2;
        *(float4*)(&Ws[r][c4]) = *(const float4*)(W + (size_t)r * ldw + col0 + c4);
    }
}

#define SM_BYTES ((128 * 65 + 64 * 64) * 4)

// ---------------- GEMM: C = [relu](A[N,64] @ W[64,64]) ----------------------
__global__ __launch_bounds__(128) void gemm128(const float* __restrict__ A,
                                               const float* __restrict__ W,
                                               float* __restrict__ C, int nrows,
                                               int relu_flag) {
    extern __shared__ float sm[];
    float (*As)[65] = (float(*)[65])sm;
    float (*Ws)[64] = (float(*)[64])(sm + 128 * 65);
    int tid = threadIdx.x;
    int row0 = blockIdx.x * 128;

    load_A_tile(As, A, row0, nrows, tid);
    load_W_tile(Ws, W, 64, 0, tid);
    __syncthreads();

    int r0 = (tid >> 3) * 8, c0 = (tid & 7) * 8;
    u64 acc[8][4] = {};
    mm_core8(As, Ws, r0, c0, acc);

    #pragma unroll
    for (int i = 0; i < 8; i++) {
        int gr = row0 + r0 + i;
        if (gr < nrows) {
            float o[8];
            #pragma unroll
            for (int jp = 0; jp < 4; jp++) unpack2(acc[i][jp], o[2 * jp], o[2 * jp + 1]);
            if (relu_flag) {
                #pragma unroll
                for (int j = 0; j < 8; j++) o[j] = fmaxf(o[j], 0.f);
            }
            float* cp = C + (size_t)gr * 64 + c0;
            *(float4*)(cp)     = make_float4(o[0], o[1], o[2], o[3]);
            *(float4*)(cp + 4) = make_float4(o[4], o[5], o[6], o[7]);
        }
    }
}

// ---------------- stage01: h = relu(Z@W2) -> h_out; T = relu(h@A1+b1) -> Tmat
// T is tf32-rounded for the MMA stage.
__global__ __launch_bounds__(128) void stage01(
        const float* __restrict__ Z, const float* __restrict__ W2,
        const float* __restrict__ A1, const float* __restrict__ b1,
        float* __restrict__ h_out, float* __restrict__ Tmat, int nrows) {
    extern __shared__ float sm[];
    float (*Hs)[65] = (float(*)[65])sm;             // Z -> h
    float (*Ws)[64] = (float(*)[64])(sm + 128 * 65);
    int tid = threadIdx.x;
    int row0 = blockIdx.x * 128;
    int r0 = (tid >> 3) * 8, c0 = (tid & 7) * 8;

    load_A_tile(Hs, Z, row0, nrows, tid);
    load_W_tile(Ws, W2, 64, 0, tid);
    __syncthreads();

    // stage 0: h = relu(Z @ W2) -> Hs and global h_out
    {
        u64 acc[8][4] = {};
        mm_core8(Hs, Ws, r0, c0, acc);
        __syncthreads();
        #pragma unroll
        for (int i = 0; i < 8; i++) {
            float o[8];
            #pragma unroll
            for (int jp = 0; jp < 4; jp++) unpack2(acc[i][jp], o[2 * jp], o[2 * jp + 1]);
            #pragma unroll
            for (int j = 0; j < 8; j++) o[j] = fmaxf(o[j], 0.f);
            #pragma unroll
            for (int j = 0; j < 8; j++) Hs[r0 + i][c0 + j] = o[j];
            int gr = row0 + r0 + i;
            if (gr < nrows) {
                float* cp = h_out + (size_t)gr * 64 + c0;
                *(float4*)(cp)     = make_float4(o[0], o[1], o[2], o[3]);
                *(float4*)(cp + 4) = make_float4(o[4], o[5], o[6], o[7]);
            }
        }
        load_W_tile(Ws, A1, 64, 0, tid);
        __syncthreads();
    }

    // stage 1: T = relu(h @ A1 + b1), tf32-rounded, to gmem
    {
        u64 acc[8][4] = {};
        mm_core8(Hs, Ws, r0, c0, acc);
        float bb[8];
        #pragma unroll
        for (int j = 0; j < 8; j++) bb[j] = b1[c0 + j];
        #pragma unroll
        for (int i = 0; i < 8; i++) {
            int gr = row0 + r0 + i;
            if (gr < nrows) {
                float o[8];
                #pragma unroll
                for (int jp = 0; jp < 4; jp++) unpack2(acc[i][jp], o[2 * jp], o[2 * jp + 1]);
                #pragma unroll
                for (int j = 0; j < 8; j++) o[j] = to_tf32(fmaxf(o[j] + bb[j], 0.f));
                float* cp = Tmat + (size_t)gr * 64 + c0;
                *(float4*)(cp)     = make_float4(o[0], o[1], o[2], o[3]);
                *(float4*)(cp + 4) = make_float4(o[4], o[5], o[6], o[7]);
            }
        }
    }
}

// ---------------- MMA stage 2: r = T @ A2 + b2 via mma.sync tf32 -------------
// 256 threads (8 warps), 128-row tile. Warp w owns rows [w*16, w*16+16).
// 6 column tiles of 64; per tile: 1 m-tile x 8 n-tiles x 8 k-steps of
// m16n8k8. Smem strides padded to 72 floats -> conflict-free fragment LDS.
#define MS_TSTRIDE 72
#define MS_SMEM ((128 * MS_TSTRIDE + 64 * MS_TSTRIDE) * 4)

__global__ __launch_bounds__(256) void mma_stage2(
        const float* __restrict__ T, const float* __restrict__ b2,
        float* __restrict__ r_out, int nrows) {
    extern __shared__ float sm[];
    float (*Ts)[MS_TSTRIDE] = (float(*)[MS_TSTRIDE])sm;
    float (*Bs)[MS_TSTRIDE] = (float(*)[MS_TSTRIDE])(sm + 128 * MS_TSTRIDE);
    int tid = threadIdx.x, wid = tid >> 5, lane = tid & 31;
    int row0 = blockIdx.x * 128;

    // load T tile [128][64]
    for (int i = tid; i < 128 * 16; i += 256) {
        int r = i >> 4, c4 = (i & 15) << 2;
        float4 v = make_float4(0.f, 0.f, 0.f, 0.f);
        int gr = row0 + r;
        if (gr < nrows) v = *(const float4*)(T + (size_t)gr * 64 + c4);
        *(float4*)(&Ts[r][c4]) = v;
    }

    int g = lane >> 2, tg = lane & 3;
    int m0 = wid * 16;
    int gr0 = row0 + m0 + g;
    int gr1 = gr0 + 8;

    for (int ct = 0; ct < 6; ct++) {
        __syncthreads();                       // prior Bs reads complete
        for (int i = tid; i < 64 * 16; i += 256) {
            int r = i >> 4, c4 = (i & 15) << 2;
            *(float4*)(&Bs[r][c4]) = *(const float4*)(g_A2t + r * 384 + ct * 64 + c4);
        }
        __syncthreads();

        float acc[8][4];
        #pragma unroll
        for (int nt = 0; nt < 8; nt++)
            #pragma unroll
            for (int q = 0; q < 4; q++) acc[nt][q] = 0.f;

        #pragma unroll
        for (int kc = 0; kc < 8; kc++) {
            int k0 = kc * 8;
            unsigned a[4];
            a[0] = __float_as_uint(Ts[m0 + g][k0 + tg]);
            a[1] = __float_as_uint(Ts[m0 + g + 8][k0 + tg]);
            a[2] = __float_as_uint(Ts[m0 + g][k0 + tg + 4]);
            a[3] = __float_as_uint(Ts[m0 + g + 8][k0 + tg + 4]);
            #pragma unroll
            for (int nt = 0; nt < 8; nt++) {
                unsigned b[2];
                b[0] = __float_as_uint(Bs[k0 + tg][nt * 8 + g]);
                b[1] = __float_as_uint(Bs[k0 + tg + 4][nt * 8 + g]);
                mma_tf32(acc[nt], a, b);
            }
        }

        // epilogue: add bias, store two rows per lane, float2 per n-tile
        #pragma unroll
        for (int nt = 0; nt < 8; nt++) {
            int gc = ct * 64 + nt * 8 + 2 * tg;
            float bx = b2[gc], by = b2[gc + 1];
            if (gr0 < nrows)
                *(float2*)(r_out + (size_t)gr0 * 384 + gc) =
                    make_float2(acc[nt][0] + bx, acc[nt][1] + by);
            if (gr1 < nrows)
                *(float2*)(r_out + (size_t)gr1 * 384 + gc) =
                    make_float2(acc[nt][2] + bx, acc[nt][3] + by);
        }
    }
}

// ---------------- launch ----------------
extern "C" void kernel_launch(void* const* d_in, const int* in_sizes, int n_in,
                              void* d_out, int out_size) {
    const float* x  = (const float*)d_in[0];
    const int*   ei = (const int*)d_in[1];
    const float* ew = (const float*)d_in[2];
    const float* W1 = (const float*)d_in[3];
    const float* W2 = (const float*)d_in[4];
    const float* A1 = (const float*)d_in[5];
    const float* b1 = (const float*)d_in[6];
    const float* A2 = (const float*)d_in[7];
    const float* b2 = (const float*)d_in[8];

    int n = in_sizes[0] / 64;       // 100000
    int e = in_sizes[2];            // 1600000
    const int* row = ei;
    const int* col = ei + e;

    float* out   = (float*)d_out;
    float* r_out = out;                       // [n, 384]
    float* h_out = out + (size_t)n * 384;     // [n, 64]

    float *bufA, *bufB;
    cudaGetSymbolAddress((void**)&bufA, g_bufA);
    cudaGetSymbolAddress((void**)&bufB, g_bufB);

    static int smem_set = 0;
    if (!smem_set) {
        cudaFuncSetAttribute(gemm128, cudaFuncAttributeMaxDynamicSharedMemorySize, SM_BYTES);
        cudaFuncSetAttribute(stage01, cudaFuncAttributeMaxDynamicSharedMemorySize, SM_BYTES);
        cudaFuncSetAttribute(mma_stage2, cudaFuncAttributeMaxDynamicSharedMemorySize, MS_SMEM);
        smem_set = 1;
    }

    int gn = (n + 255) / 256;
    int ge = (e + 255) / 256;
    int nb = (n + 1023) / 1024;
    int mt = (n + 127) / 128;
    int gagg = (n * 32 + 255) / 256;

    // CSR-by-target build (shared by both GCN layers)
    k_init<<<gn, 256>>>(n);
    k_count<<<ge, 256>>>(col, ew, e);
    k_scan1<<<nb, 1024>>>(n);
    k_scan2<<<1, 128>>>(nb);
    k_scan3<<<gn, 256>>>(n, e);
    k_build<<<ge, 256>>>(row, col, ew, e);
    k_tr<<<(64 * 384 + 255) / 256, 256>>>(A2);

    // Layer 1 (reassociated): Y = S·x ; h1 = relu(Y @ W1)
    k_agg<<<gagg, 256>>>(x, bufA, n);
    gemm128<<<mt, 128, SM_BYTES>>>(bufA, W1, bufB, n, 1);

    // Layer 2 + readout stages 0/1: Z = S·h1 ; h = relu(Z@W2) ; T = relu(h@A1+b1)
    k_agg<<<gagg, 256>>>(bufB, bufA, n);
    stage01<<<mt, 128, SM_BYTES>>>(bufA, W2, A1, b1, h_out, bufB, n);

    // Readout stage 2 on tensor cores (legacy mma.sync tf32): r = T @ A2 + b2
    mma_stage2<<<mt, 256, MS_SMEM>>>(bufB, b2, r_out, n);
}